// round 9
// baseline (speedup 1.0000x reference)
#include <cuda_runtime.h>
#include <cuda_bf16.h>
#include <cstdint>

// ---------------- problem dims ----------------
#define TOKENS 8192
#define OUTF   4096
#define INF    4096
#define GROUPS 512
#define LUTK   16
#define VEC    8

// ---------------- GEMM tiling (int8) ----------------
#define MTILE  128
#define NTILE  128
#define BKB    64                   // int8 K bytes per chunk (two k32 MMA steps)
#define NCHUNKS (INF / BKB)         // 64
#define ROWB   80                   // padded smem row bytes (64 data + 16 pad) -> conflict-free ldsm
#define TILEB  (128 * ROWB)         // 10240 per 128-row tile
#define OFF_A1 0
#define OFF_A0 (1 * TILEB)
#define OFF_B1 (2 * TILEB)
#define OFF_B0 (3 * TILEB)
#define STAGEB (4 * TILEB)          // 40960
#define NSTAGE 3
#define SMEM_BYTES (NSTAGE * STAGEB)   // 122880

#define QMAX 16300.0f               // |q| budget: x1 in [-127,127], x0 in [-64,64]

// ---------------- device scratch (allocation-free rule: __device__ globals) ----------------
__device__ int8_t g_x1[TOKENS * INF];
__device__ int8_t g_x0[TOKENS * INF];
__device__ int8_t g_w1[OUTF * INF];
__device__ int8_t g_w0[OUTF * INF];
__device__ float  g_wf[OUTF * INF];     // f32 mixed weight (pre-quant)
__device__ float  g_sx[TOKENS];
__device__ float  g_sw[OUTF];

// ---------------- PTX helpers (base compute_103 target: NO tcgen05/TMEM) ----------------
static __device__ __forceinline__ uint32_t smem_u32(const void* p) {
    uint32_t a;
    asm("{ .reg .u64 t; cvta.to.shared.u64 t, %1; cvt.u32.u64 %0, t; }" : "=r"(a) : "l"(p));
    return a;
}

#define CP16(smem_addr, gptr) \
    asm volatile("cp.async.cg.shared.global [%0], [%1], 16;" \
                 :: "r"(smem_addr), "l"(gptr) : "memory")
#define CP_COMMIT() asm volatile("cp.async.commit_group;" ::: "memory")
#define CP_WAIT1()  asm volatile("cp.async.wait_group 1;" ::: "memory")
#define CP_WAIT0()  asm volatile("cp.async.wait_group 0;" ::: "memory")

#define LDSM_X4(r0, r1, r2, r3, addr) \
    asm volatile("ldmatrix.sync.aligned.m8n8.x4.shared.b16 {%0,%1,%2,%3}, [%4];" \
                 : "=r"(r0), "=r"(r1), "=r"(r2), "=r"(r3) : "r"(addr))

// s8 IMMA: D(s32) += A(s8 m16k32, row) * B(s8 k32n8, col)
#define MMA_S8(d, a, b) \
    asm volatile("mma.sync.aligned.m16n8k32.row.col.s32.s8.s8.s32 " \
                 "{%0,%1,%2,%3}, {%4,%5,%6,%7}, {%8,%9}, {%0,%1,%2,%3};" \
                 : "+r"((d)[0]), "+r"((d)[1]), "+r"((d)[2]), "+r"((d)[3]) \
                 : "r"((a)[0]), "r"((a)[1]), "r"((a)[2]), "r"((a)[3]), \
                   "r"((b)[0]), "r"((b)[1]))

// ---------------- row quantizer: f32 row -> (q1, q0) int8 + scale ----------------
// q = round(v/s), |q| <= ~QMAX;  q1 = (q+64)>>7 in [-127,127];  q0 = q - 128*q1 in [-64,64].
static __device__ __forceinline__ void quant_row(const float* __restrict__ src,
                                                 int8_t* __restrict__ q1,
                                                 int8_t* __restrict__ q0,
                                                 float* __restrict__ scale,
                                                 int row) {
    __shared__ float red[256];
    const int t = threadIdx.x;
    const float4* sr = (const float4*)(src + (size_t)row * INF);

    float4 v[4];
    float amax = 0.f;
#pragma unroll
    for (int i = 0; i < 4; ++i) {
        v[i] = sr[i * 256 + t];
        amax = fmaxf(amax, fmaxf(fmaxf(fabsf(v[i].x), fabsf(v[i].y)),
                                 fmaxf(fabsf(v[i].z), fabsf(v[i].w))));
    }
    red[t] = amax;
    __syncthreads();
#pragma unroll
    for (int s = 128; s > 0; s >>= 1) {
        if (t < s) red[t] = fmaxf(red[t], red[t + s]);
        __syncthreads();
    }
    const float m = fmaxf(red[0], 1e-30f);
    const float inv = QMAX / m;
    if (t == 0) scale[row] = m / QMAX;

    char4* d1 = (char4*)(q1 + (size_t)row * INF);
    char4* d0 = (char4*)(q0 + (size_t)row * INF);
#pragma unroll
    for (int i = 0; i < 4; ++i) {
        float f[4] = {v[i].x, v[i].y, v[i].z, v[i].w};
        char c1[4], c0[4];
#pragma unroll
        for (int j = 0; j < 4; ++j) {
            int q = __float2int_rn(f[j] * inv);
            int hi = (q + 64) >> 7;
            c1[j] = (char)hi;
            c0[j] = (char)(q - (hi << 7));
        }
        d1[i * 256 + t] = make_char4(c1[0], c1[1], c1[2], c1[3]);
        d0[i * 256 + t] = make_char4(c0[0], c0[1], c0[2], c0[3]);
    }
}

__global__ void __launch_bounds__(256) quant_x_kernel(const float* __restrict__ x) {
    quant_row(x, g_x1, g_x0, g_sx, blockIdx.x);
}
__global__ void __launch_bounds__(256) quant_w_kernel() {
    quant_row(g_wf, g_w1, g_w0, g_sw, blockIdx.x);
}

// ---------------- build weight (softmax-LUT mix -> f32) ----------------
// g fastest within a warp: coalesced logits reads and coalesced g_wf writes.
__global__ void __launch_bounds__(256) build_w_kernel(const float* __restrict__ logits,
                                                      const float* __restrict__ luts) {
    int idx = blockIdx.x * blockDim.x + threadIdx.x;   // 0 .. 2097151
    int g = idx & (GROUPS - 1);
    int o = idx >> 9;

    float acc[VEC];
#pragma unroll
    for (int v = 0; v < VEC; ++v) acc[v] = 0.f;

#pragma unroll
    for (int n = 0; n < 2; ++n) {
        const float4* lg = (const float4*)(logits + (((size_t)n * OUTF + o) * GROUPS + g) * LUTK);
        float4 t0 = lg[0], t1 = lg[1], t2 = lg[2], t3 = lg[3];
        float l[LUTK] = {t0.x, t0.y, t0.z, t0.w, t1.x, t1.y, t1.z, t1.w,
                         t2.x, t2.y, t2.z, t2.w, t3.x, t3.y, t3.z, t3.w};
        float m = l[0];
#pragma unroll
        for (int k = 1; k < LUTK; ++k) m = fmaxf(m, l[k]);
        float s = 0.f;
#pragma unroll
        for (int k = 0; k < LUTK; ++k) { l[k] = __expf(l[k] - m); s += l[k]; }
        float inv = __frcp_rn(s);
        const float4* lut4 = (const float4*)(luts + ((size_t)n * GROUPS + g) * LUTK * VEC);
#pragma unroll
        for (int k = 0; k < LUTK; ++k) {
            float wgt = l[k] * inv;
            float4 a = lut4[k * 2 + 0];
            float4 b = lut4[k * 2 + 1];
            acc[0] += wgt * a.x; acc[1] += wgt * a.y; acc[2] += wgt * a.z; acc[3] += wgt * a.w;
            acc[4] += wgt * b.x; acc[5] += wgt * b.y; acc[6] += wgt * b.z; acc[7] += wgt * b.w;
        }
    }

    float4* wrow = (float4*)(g_wf + (size_t)o * INF + g * VEC);
    wrow[0] = make_float4(acc[0], acc[1], acc[2], acc[3]);
    wrow[1] = make_float4(acc[4], acc[5], acc[6], acc[7]);
}

// ---------------- int8 double-split IMMA GEMM ----------------
// out[m,n] = sx[m]*sw[n]*(16384*hi + 128*corr) + bias[n]
// hi = x1*w1;  corr = x1*w0 + x0*w1 (shared accumulator; x0*w0 dropped ~1e-4 rel).
// 128x128 CTA tile, 8 warps (2 M x 4 N, warp tile 64x32), BK=64B, 3-stage cp.async ring.
__global__ void __launch_bounds__(256, 1)
gemm_int8_kernel(const float* __restrict__ bias, float* __restrict__ out) {
    extern __shared__ char smem[];
    uint32_t sbase = smem_u32(smem);

    const int tid  = threadIdx.x;
    const int wid  = tid >> 5;
    const int lane = tid & 31;
    const int wm   = wid >> 2;       // 0..1 (64 rows each)
    const int wn   = wid & 3;        // 0..3 (32 cols each)

    const int m0 = blockIdx.y * MTILE;
    const int n0 = blockIdx.x * NTILE;

    // ldmatrix per-lane offsets (same 8x16B matrix decomposition as bf16 16x16 frags)
    const int g8 = lane >> 3, r8 = lane & 7;
    const uint32_t aOff = (uint32_t)(((g8 & 1) * 8 + r8) * ROWB + (g8 >> 1) * 16);
    const uint32_t bOff = (uint32_t)(((g8 >> 1) * 8 + r8) * ROWB + (g8 & 1) * 16);
    const uint32_t wmRow = (uint32_t)(wm * 64 * ROWB);
    const uint32_t wnRow = (uint32_t)(wn * 32 * ROWB);

    // cp.async mapping: 2 threads per row, 32B halves
    const int ldRow = tid >> 1;
    const uint32_t half = (uint32_t)(tid & 1) * 32u;
    const char* px1 = (const char*)(g_x1 + (size_t)(m0 + ldRow) * INF);
    const char* px0 = (const char*)(g_x0 + (size_t)(m0 + ldRow) * INF);
    const char* pw1 = (const char*)(g_w1 + (size_t)(n0 + ldRow) * INF);
    const char* pw0 = (const char*)(g_w0 + (size_t)(n0 + ldRow) * INF);
    const uint32_t dst = sbase + (uint32_t)ldRow * ROWB + half;

    int acc_h[4][4][4], acc_c[4][4][4];
#pragma unroll
    for (int mt = 0; mt < 4; ++mt)
#pragma unroll
        for (int nt = 0; nt < 4; ++nt)
#pragma unroll
            for (int e = 0; e < 4; ++e) { acc_h[mt][nt][e] = 0; acc_c[mt][nt][e] = 0; }

    auto load_chunk = [&](int c, int s) {
        uint32_t sb = (uint32_t)s * STAGEB;
        size_t go = (size_t)c * BKB + half;
#pragma unroll
        for (int q = 0; q < 2; ++q) {
            CP16(dst + sb + OFF_A1 + q * 16, px1 + go + q * 16);
            CP16(dst + sb + OFF_A0 + q * 16, px0 + go + q * 16);
            CP16(dst + sb + OFF_B1 + q * 16, pw1 + go + q * 16);
            CP16(dst + sb + OFF_B0 + q * 16, pw0 + go + q * 16);
        }
        CP_COMMIT();
    };

    load_chunk(0, 0);
    load_chunk(1, 1);

    for (int c = 0; c < NCHUNKS; ++c) {
        if (c + 2 < NCHUNKS) CP_WAIT1(); else CP_WAIT0();
        __syncthreads();
        if (c + 2 < NCHUNKS) load_chunk(c + 2, (c + 2) % NSTAGE);

        const uint32_t st = sbase + (uint32_t)(c % NSTAGE) * STAGEB;
#pragma unroll
        for (int ks = 0; ks < 2; ++ks) {
            const uint32_t kofs = (uint32_t)ks * 32;
            uint32_t A1[4][4], A0[4][4], B1[4][2], B0[4][2];
#pragma unroll
            for (int mt = 0; mt < 4; ++mt) {
                uint32_t a = st + wmRow + (uint32_t)(mt * 16 * ROWB) + aOff + kofs;
                LDSM_X4(A1[mt][0], A1[mt][1], A1[mt][2], A1[mt][3], a + OFF_A1);
                LDSM_X4(A0[mt][0], A0[mt][1], A0[mt][2], A0[mt][3], a + OFF_A0);
            }
#pragma unroll
            for (int np = 0; np < 2; ++np) {
                uint32_t b = st + wnRow + (uint32_t)(np * 16 * ROWB) + bOff + kofs;
                uint32_t r0, r1, r2, r3;
                LDSM_X4(r0, r1, r2, r3, b + OFF_B1);
                B1[np * 2][0] = r0; B1[np * 2][1] = r1;
                B1[np * 2 + 1][0] = r2; B1[np * 2 + 1][1] = r3;
                LDSM_X4(r0, r1, r2, r3, b + OFF_B0);
                B0[np * 2][0] = r0; B0[np * 2][1] = r1;
                B0[np * 2 + 1][0] = r2; B0[np * 2 + 1][1] = r3;
            }
            // pass-major: consecutive MMAs never share an accumulator (16-deep independence)
#pragma unroll
            for (int mt = 0; mt < 4; ++mt)
#pragma unroll
                for (int nt = 0; nt < 4; ++nt)
                    MMA_S8(acc_h[mt][nt], A1[mt], B1[nt]);
#pragma unroll
            for (int mt = 0; mt < 4; ++mt)
#pragma unroll
                for (int nt = 0; nt < 4; ++nt)
                    MMA_S8(acc_c[mt][nt], A1[mt], B0[nt]);
#pragma unroll
            for (int mt = 0; mt < 4; ++mt)
#pragma unroll
                for (int nt = 0; nt < 4; ++nt)
                    MMA_S8(acc_c[mt][nt], A0[mt], B1[nt]);
        }
    }

    // ---- epilogue: scales + bias ----
    const int cgl = (lane & 3) * 2;
    const int r0l = lane >> 2;
    const int ncol = n0 + wn * 32 + cgl;

    float2 swv[4], bv[4];
#pragma unroll
    for (int nt = 0; nt < 4; ++nt) {
        swv[nt] = *(const float2*)(g_sw + ncol + nt * 8);
        bv[nt]  = *(const float2*)(bias + ncol + nt * 8);
    }

#pragma unroll
    for (int mt = 0; mt < 4; ++mt) {
        const int rowA = m0 + wm * 64 + mt * 16 + r0l;
        const float sxA = g_sx[rowA];
        const float sxB = g_sx[rowA + 8];
        float* pA = out + (size_t)rowA * OUTF + ncol;
        float* pB = pA + (size_t)8 * OUTF;
#pragma unroll
        for (int nt = 0; nt < 4; ++nt) {
            float f0 = 16384.f * (float)acc_h[mt][nt][0] + 128.f * (float)acc_c[mt][nt][0];
            float f1 = 16384.f * (float)acc_h[mt][nt][1] + 128.f * (float)acc_c[mt][nt][1];
            float f2 = 16384.f * (float)acc_h[mt][nt][2] + 128.f * (float)acc_c[mt][nt][2];
            float f3 = 16384.f * (float)acc_h[mt][nt][3] + 128.f * (float)acc_c[mt][nt][3];
            float2 vA = {fmaf(f0, sxA * swv[nt].x, bv[nt].x),
                         fmaf(f1, sxA * swv[nt].y, bv[nt].y)};
            float2 vB = {fmaf(f2, sxB * swv[nt].x, bv[nt].x),
                         fmaf(f3, sxB * swv[nt].y, bv[nt].y)};
            *(float2*)(pA + nt * 8) = vA;
            *(float2*)(pB + nt * 8) = vB;
        }
    }
}

// ---------------- launcher ----------------
extern "C" void kernel_launch(void* const* d_in, const int* in_sizes, int n_in,
                              void* d_out, int out_size) {
    const float* x      = (const float*)d_in[0];
    const float* logits = (const float*)d_in[1];
    const float* luts   = (const float*)d_in[2];
    const float* bias   = (const float*)d_in[3];
    float* out          = (float*)d_out;
    (void)in_sizes; (void)n_in; (void)out_size;

    build_w_kernel<<<(OUTF * GROUPS) / 256, 256>>>(logits, luts);
    quant_x_kernel<<<TOKENS, 256>>>(x);
    quant_w_kernel<<<OUTF, 256>>>();

    cudaFuncSetAttribute(gemm_int8_kernel, cudaFuncAttributeMaxDynamicSharedMemorySize, SMEM_BYTES);
    dim3 grid(OUTF / NTILE, TOKENS / MTILE);   // (32, 64): n fast -> W stays L2-resident
    gemm_int8_kernel<<<grid, 256, SMEM_BYTES>>>(bias, out);
}

// round 10
// speedup vs baseline: 3.8883x; 3.8883x over previous
#include <cuda_runtime.h>
#include <cuda_fp16.h>
#include <cstdint>

// ---------------- problem dims ----------------
#define TOKENS 8192
#define OUTF   4096
#define INF    4096
#define GROUPS 512
#define LUTK   16
#define VEC    8

// ---------------- GEMM tiling ----------------
#define MTILE  256
#define NTILE  128
#define BK     32                   // f16 K elements per chunk (64B data per row)
#define NCHUNKS (INF / BK)          // 128
#define ROWB   80                   // padded smem row bytes (64 data + 16 pad) -> conflict-free ldsm
#define ATILEB (256 * ROWB)         // 20480
#define BTILEB (128 * ROWB)         // 10240
#define OFF_A  0
#define OFF_B  (ATILEB)
#define STAGEB (ATILEB + BTILEB)    // 30720
#define NSTAGE 3
#define SMEM_BYTES (NSTAGE * STAGEB)   // 92160

// ---------------- device scratch (allocation-free rule: __device__ globals) ----------------
__device__ __half g_xh[TOKENS * INF];
__device__ __half g_wh[OUTF * INF];

// ---------------- PTX helpers (base compute_103 target: NO tcgen05/TMEM) ----------------
static __device__ __forceinline__ uint32_t smem_u32(const void* p) {
    uint32_t a;
    asm("{ .reg .u64 t; cvta.to.shared.u64 t, %1; cvt.u32.u64 %0, t; }" : "=r"(a) : "l"(p));
    return a;
}

#define CP16(smem_addr, gptr) \
    asm volatile("cp.async.cg.shared.global [%0], [%1], 16;" \
                 :: "r"(smem_addr), "l"(gptr) : "memory")
#define CP_COMMIT() asm volatile("cp.async.commit_group;" ::: "memory")
#define CP_WAIT1()  asm volatile("cp.async.wait_group 1;" ::: "memory")
#define CP_WAIT0()  asm volatile("cp.async.wait_group 0;" ::: "memory")

#define LDSM_X4(r0, r1, r2, r3, addr) \
    asm volatile("ldmatrix.sync.aligned.m8n8.x4.shared.b16 {%0,%1,%2,%3}, [%4];" \
                 : "=r"(r0), "=r"(r1), "=r"(r2), "=r"(r3) : "r"(addr))

#define MMA_F16(d, a, b) \
    asm volatile("mma.sync.aligned.m16n8k16.row.col.f32.f16.f16.f32 " \
                 "{%0,%1,%2,%3}, {%4,%5,%6,%7}, {%8,%9}, {%0,%1,%2,%3};" \
                 : "+f"((d)[0]), "+f"((d)[1]), "+f"((d)[2]), "+f"((d)[3]) \
                 : "r"((a)[0]), "r"((a)[1]), "r"((a)[2]), "r"((a)[3]), \
                   "r"((b)[0]), "r"((b)[1]))

// ---------------- Kernel 1: convert x (fp32 -> fp16) ----------------
__global__ void __launch_bounds__(256) convert_x_kernel(const float* __restrict__ x) {
    int gid = blockIdx.x * blockDim.x + threadIdx.x;   // float4 index
    float4 v = ((const float4*)x)[gid];
    __half2 h01 = __floats2half2_rn(v.x, v.y);
    __half2 h23 = __floats2half2_rn(v.z, v.w);
    uint2 u;
    u.x = *reinterpret_cast<unsigned int*>(&h01);
    u.y = *reinterpret_cast<unsigned int*>(&h23);
    ((uint2*)g_xh)[gid] = u;
}

// ---------------- Kernel 2: build weight (softmax-LUT mix -> fp16) ----------------
// g fastest within a warp: coalesced logits reads and coalesced g_wh writes.
__global__ void __launch_bounds__(256) build_w_kernel(const float* __restrict__ logits,
                                                      const float* __restrict__ luts) {
    int idx = blockIdx.x * blockDim.x + threadIdx.x;   // 0 .. 2097151
    int g = idx & (GROUPS - 1);
    int o = idx >> 9;

    float acc[VEC];
#pragma unroll
    for (int v = 0; v < VEC; ++v) acc[v] = 0.f;

#pragma unroll
    for (int n = 0; n < 2; ++n) {
        const float4* lg = (const float4*)(logits + (((size_t)n * OUTF + o) * GROUPS + g) * LUTK);
        float4 t0 = lg[0], t1 = lg[1], t2 = lg[2], t3 = lg[3];
        float l[LUTK] = {t0.x, t0.y, t0.z, t0.w, t1.x, t1.y, t1.z, t1.w,
                         t2.x, t2.y, t2.z, t2.w, t3.x, t3.y, t3.z, t3.w};
        float m = l[0];
#pragma unroll
        for (int k = 1; k < LUTK; ++k) m = fmaxf(m, l[k]);
        float s = 0.f;
#pragma unroll
        for (int k = 0; k < LUTK; ++k) { l[k] = __expf(l[k] - m); s += l[k]; }
        float inv = __frcp_rn(s);
        const float4* lut4 = (const float4*)(luts + ((size_t)n * GROUPS + g) * LUTK * VEC);
#pragma unroll
        for (int k = 0; k < LUTK; ++k) {
            float wgt = l[k] * inv;
            float4 a = lut4[k * 2 + 0];
            float4 b = lut4[k * 2 + 1];
            acc[0] += wgt * a.x; acc[1] += wgt * a.y; acc[2] += wgt * a.z; acc[3] += wgt * a.w;
            acc[4] += wgt * b.x; acc[5] += wgt * b.y; acc[6] += wgt * b.z; acc[7] += wgt * b.w;
        }
    }

    union { uint4 u; __half2 h2[4]; } pk;
    pk.h2[0] = __floats2half2_rn(acc[0], acc[1]);
    pk.h2[1] = __floats2half2_rn(acc[2], acc[3]);
    pk.h2[2] = __floats2half2_rn(acc[4], acc[5]);
    pk.h2[3] = __floats2half2_rn(acc[6], acc[7]);
    ((uint4*)g_wh)[(size_t)o * (INF / 8) + g] = pk.u;
}

// ---------------- Kernel 3: single-pass f16 HMMA GEMM ----------------
// C[8192,4096] = Xh @ Wh^T + bias  (f16 inputs, f32 accumulate; rel_err ~4e-4).
// 256x128 CTA tile, BK=32, 8 warps (4x2 grid, warp tile 64x64), 3-stage cp.async ring,
// ONE __syncthreads per chunk.
__global__ void __launch_bounds__(256, 1)
gemm_f16_kernel(const float* __restrict__ bias, float* __restrict__ out) {
    extern __shared__ char smem[];
    uint32_t sbase = smem_u32(smem);

    const int tid  = threadIdx.x;
    const int wid  = tid >> 5;
    const int lane = tid & 31;
    const int wm   = wid >> 1;       // 0..3  (M warp row, 64 rows each)
    const int wn   = wid & 1;        // 0..1  (N warp col, 64 cols each)

    const int m0 = blockIdx.y * MTILE;
    const int n0 = blockIdx.x * NTILE;

    // ---- per-lane ldmatrix address offsets (within a 16x16 frag at 80B rows) ----
    const int g8 = lane >> 3, r8 = lane & 7;
    const uint32_t aOff = (uint32_t)(((g8 & 1) * 8 + r8) * ROWB + (g8 >> 1) * 16);
    const uint32_t bOff = (uint32_t)(((g8 >> 1) * 8 + r8) * ROWB + (g8 & 1) * 16);
    const uint32_t wmRow = (uint32_t)(wm * 64 * ROWB);
    const uint32_t wnRow = (uint32_t)(wn * 64 * ROWB);

    // ---- gmem sources for cp.async ----
    // A: thread -> row tid (0..255), 4x16B.  B: row tid>>1, half (tid&1)*32B, 2x16B.
    const char* px = (const char*)(g_xh + (size_t)(m0 + tid) * INF);
    const char* pw = (const char*)(g_wh + (size_t)(n0 + (tid >> 1)) * INF);
    const uint32_t aDst = sbase + (uint32_t)tid * ROWB;
    const uint32_t bDst = sbase + (uint32_t)(tid >> 1) * ROWB + (uint32_t)(tid & 1) * 32u;
    const uint32_t bSrcOff = (uint32_t)(tid & 1) * 32u;

    float acc[4][8][4];
#pragma unroll
    for (int mt = 0; mt < 4; ++mt)
#pragma unroll
        for (int nt = 0; nt < 8; ++nt)
#pragma unroll
            for (int e = 0; e < 4; ++e) acc[mt][nt][e] = 0.f;

    auto load_chunk = [&](int c, int s) {
        uint32_t sb = (uint32_t)s * STAGEB;
        size_t go = (size_t)c * (BK * 2);   // byte offset within a K row
#pragma unroll
        for (int q = 0; q < 4; ++q)
            CP16(aDst + sb + OFF_A + q * 16, px + go + q * 16);
#pragma unroll
        for (int q = 0; q < 2; ++q)
            CP16(bDst + sb + OFF_B + q * 16, pw + go + bSrcOff + q * 16);
        CP_COMMIT();
    };

    load_chunk(0, 0);
    load_chunk(1, 1);

    for (int c = 0; c < NCHUNKS; ++c) {
        if (c + 2 < NCHUNKS) CP_WAIT1(); else CP_WAIT0();
        __syncthreads();
        if (c + 2 < NCHUNKS) load_chunk(c + 2, (c + 2) % NSTAGE);

        const uint32_t st = sbase + (uint32_t)(c % NSTAGE) * STAGEB;
#pragma unroll
        for (int ks = 0; ks < 2; ++ks) {
            const uint32_t kofs = (uint32_t)ks * 32;
            uint32_t A[4][4], B[8][2];
#pragma unroll
            for (int mt = 0; mt < 4; ++mt) {
                uint32_t a = st + OFF_A + wmRow + (uint32_t)(mt * 16 * ROWB) + aOff + kofs;
                LDSM_X4(A[mt][0], A[mt][1], A[mt][2], A[mt][3], a);
            }
#pragma unroll
            for (int nt2 = 0; nt2 < 4; ++nt2) {
                uint32_t b = st + OFF_B + wnRow + (uint32_t)(nt2 * 16 * ROWB) + bOff + kofs;
                uint32_t r0, r1, r2, r3;
                LDSM_X4(r0, r1, r2, r3, b);
                B[nt2 * 2][0] = r0; B[nt2 * 2][1] = r1;
                B[nt2 * 2 + 1][0] = r2; B[nt2 * 2 + 1][1] = r3;
            }
            // consecutive MMAs never share an accumulator (32-deep independence)
#pragma unroll
            for (int mt = 0; mt < 4; ++mt)
#pragma unroll
                for (int nt = 0; nt < 8; ++nt)
                    MMA_F16(acc[mt][nt], A[mt], B[nt]);
        }
    }

    // ---- epilogue: acc + bias -> out ----
    const int cgl = (lane & 3) * 2;
    const int r0l = lane >> 2;
    const float* bp = bias + n0 + wn * 64 + cgl;
    float2 bv[8];
#pragma unroll
    for (int nt = 0; nt < 8; ++nt) bv[nt] = *(const float2*)(bp + nt * 8);

#pragma unroll
    for (int mt = 0; mt < 4; ++mt) {
        size_t row = (size_t)(m0 + wm * 64 + mt * 16 + r0l);
        float* p0 = out + row * OUTF + n0 + wn * 64 + cgl;
        float* p1 = p0 + (size_t)8 * OUTF;
#pragma unroll
        for (int nt = 0; nt < 8; ++nt) {
            float2 v0 = {acc[mt][nt][0] + bv[nt].x, acc[mt][nt][1] + bv[nt].y};
            float2 v1 = {acc[mt][nt][2] + bv[nt].x, acc[mt][nt][3] + bv[nt].y};
            *(float2*)(p0 + nt * 8) = v0;
            *(float2*)(p1 + nt * 8) = v1;
        }
    }
}

// ---------------- launcher ----------------
extern "C" void kernel_launch(void* const* d_in, const int* in_sizes, int n_in,
                              void* d_out, int out_size) {
    const float* x      = (const float*)d_in[0];
    const float* logits = (const float*)d_in[1];
    const float* luts   = (const float*)d_in[2];
    const float* bias   = (const float*)d_in[3];
    float* out          = (float*)d_out;
    (void)in_sizes; (void)n_in; (void)out_size;

    convert_x_kernel<<<(TOKENS * INF / 4) / 256, 256>>>(x);
    build_w_kernel<<<(OUTF * GROUPS) / 256, 256>>>(logits, luts);

    cudaFuncSetAttribute(gemm_f16_kernel, cudaFuncAttributeMaxDynamicSharedMemorySize, SMEM_BYTES);
    dim3 grid(OUTF / NTILE, TOKENS / MTILE);   // (32, 32): n fast -> W stays L2-resident
    gemm_f16_kernel<<<grid, 256, SMEM_BYTES>>>(bias, out);
}

// round 11
// speedup vs baseline: 4.6051x; 1.1844x over previous
#include <cuda_runtime.h>
#include <cuda_fp16.h>
#include <cstdint>

// ---------------- problem dims ----------------
#define TOKENS 8192
#define OUTF   4096
#define INF    4096
#define GROUPS 512
#define LUTK   16
#define VEC    8

// ---------------- GEMM tiling ----------------
#define MTILE  256
#define NTILE  128
#define BK     32                   // f16 K elements per chunk (64B data per row)
#define NCHUNKS (INF / BK)          // 128
#define ROWB   80                   // padded smem row bytes (64 data + 16 pad) -> conflict-free ldsm
#define ATILEB (256 * ROWB)         // 20480
#define BTILEB (128 * ROWB)         // 10240
#define OFF_A  0
#define OFF_B  (ATILEB)
#define STAGEB (ATILEB + BTILEB)    // 30720
#define NSTAGE 3
#define SMEM_BYTES (NSTAGE * STAGEB)   // 92160

// ---------------- device scratch (allocation-free rule: __device__ globals) ----------------
__device__ __half g_xh[TOKENS * INF];
__device__ __half g_wh[OUTF * INF];

// ---------------- PTX helpers (base compute_103 target: NO tcgen05/TMEM) ----------------
static __device__ __forceinline__ uint32_t smem_u32(const void* p) {
    uint32_t a;
    asm("{ .reg .u64 t; cvta.to.shared.u64 t, %1; cvt.u32.u64 %0, t; }" : "=r"(a) : "l"(p));
    return a;
}

#define CP16(smem_addr, gptr) \
    asm volatile("cp.async.cg.shared.global [%0], [%1], 16;" \
                 :: "r"(smem_addr), "l"(gptr) : "memory")
#define CP_COMMIT() asm volatile("cp.async.commit_group;" ::: "memory")
#define CP_WAIT1()  asm volatile("cp.async.wait_group 1;" ::: "memory")
#define CP_WAIT0()  asm volatile("cp.async.wait_group 0;" ::: "memory")

#define LDSM_X4(r0, r1, r2, r3, addr) \
    asm volatile("ldmatrix.sync.aligned.m8n8.x4.shared.b16 {%0,%1,%2,%3}, [%4];" \
                 : "=r"(r0), "=r"(r1), "=r"(r2), "=r"(r3) : "r"(addr))

#define MMA_F16(d, a, b) \
    asm volatile("mma.sync.aligned.m16n8k16.row.col.f32.f16.f16.f32 " \
                 "{%0,%1,%2,%3}, {%4,%5,%6,%7}, {%8,%9}, {%0,%1,%2,%3};" \
                 : "+f"((d)[0]), "+f"((d)[1]), "+f"((d)[2]), "+f"((d)[3]) \
                 : "r"((a)[0]), "r"((a)[1]), "r"((a)[2]), "r"((a)[3]), \
                   "r"((b)[0]), "r"((b)[1]))

// ---------------- Kernel 1: convert x (fp32 -> fp16) ----------------
__global__ void __launch_bounds__(256) convert_x_kernel(const float* __restrict__ x) {
    int gid = blockIdx.x * blockDim.x + threadIdx.x;   // float4 index
    float4 v = ((const float4*)x)[gid];
    __half2 h01 = __floats2half2_rn(v.x, v.y);
    __half2 h23 = __floats2half2_rn(v.z, v.w);
    uint2 u;
    u.x = *reinterpret_cast<unsigned int*>(&h01);
    u.y = *reinterpret_cast<unsigned int*>(&h23);
    ((uint2*)g_xh)[gid] = u;
}

// ---------------- Kernel 2: build weight (softmax-LUT mix -> fp16) ----------------
__global__ void __launch_bounds__(256) build_w_kernel(const float* __restrict__ logits,
                                                      const float* __restrict__ luts) {
    int idx = blockIdx.x * blockDim.x + threadIdx.x;   // g fastest: coalesced
    int g = idx & (GROUPS - 1);
    int o = idx >> 9;

    float acc[VEC];
#pragma unroll
    for (int v = 0; v < VEC; ++v) acc[v] = 0.f;

#pragma unroll
    for (int n = 0; n < 2; ++n) {
        const float4* lg = (const float4*)(logits + (((size_t)n * OUTF + o) * GROUPS + g) * LUTK);
        float4 t0 = lg[0], t1 = lg[1], t2 = lg[2], t3 = lg[3];
        float l[LUTK] = {t0.x, t0.y, t0.z, t0.w, t1.x, t1.y, t1.z, t1.w,
                         t2.x, t2.y, t2.z, t2.w, t3.x, t3.y, t3.z, t3.w};
        float m = l[0];
#pragma unroll
        for (int k = 1; k < LUTK; ++k) m = fmaxf(m, l[k]);
        float s = 0.f;
#pragma unroll
        for (int k = 0; k < LUTK; ++k) { l[k] = __expf(l[k] - m); s += l[k]; }
        float inv = __frcp_rn(s);
        const float4* lut4 = (const float4*)(luts + ((size_t)n * GROUPS + g) * LUTK * VEC);
#pragma unroll
        for (int k = 0; k < LUTK; ++k) {
            float wgt = l[k] * inv;
            float4 a = lut4[k * 2 + 0];
            float4 b = lut4[k * 2 + 1];
            acc[0] += wgt * a.x; acc[1] += wgt * a.y; acc[2] += wgt * a.z; acc[3] += wgt * a.w;
            acc[4] += wgt * b.x; acc[5] += wgt * b.y; acc[6] += wgt * b.z; acc[7] += wgt * b.w;
        }
    }

    union { uint4 u; __half2 h2[4]; } pk;
    pk.h2[0] = __floats2half2_rn(acc[0], acc[1]);
    pk.h2[1] = __floats2half2_rn(acc[2], acc[3]);
    pk.h2[2] = __floats2half2_rn(acc[4], acc[5]);
    pk.h2[3] = __floats2half2_rn(acc[6], acc[7]);
    ((uint4*)g_wh)[(size_t)o * (INF / 8) + g] = pk.u;
}

// ---------------- Kernel 3: single-pass f16 HMMA GEMM, 16 warps ----------------
// C[8192,4096] = Xh @ Wh^T + bias  (f16 in, f32 accum; rel_err ~3e-4).
// 256x128 CTA tile, BK=32, 16 warps (4x4 grid, warp tile 64x32) -> 4 warps/SMSP
// for latency hiding. 3-stage cp.async ring, ONE __syncthreads per chunk.
__global__ void __launch_bounds__(512, 1)
gemm_f16_kernel(const float* __restrict__ bias, float* __restrict__ out) {
    extern __shared__ char smem[];
    uint32_t sbase = smem_u32(smem);

    const int tid  = threadIdx.x;
    const int wid  = tid >> 5;
    const int lane = tid & 31;
    const int wm   = wid >> 2;       // 0..3  (M warp row, 64 rows each)
    const int wn   = wid & 3;        // 0..3  (N warp col, 32 cols each)

    const int m0 = blockIdx.y * MTILE;
    const int n0 = blockIdx.x * NTILE;

    // ---- per-lane ldmatrix address offsets (within a 16x16 frag at 80B rows) ----
    const int g8 = lane >> 3, r8 = lane & 7;
    const uint32_t aOff = (uint32_t)(((g8 & 1) * 8 + r8) * ROWB + (g8 >> 1) * 16);
    const uint32_t bOff = (uint32_t)(((g8 >> 1) * 8 + r8) * ROWB + (g8 & 1) * 16);
    const uint32_t wmRow = (uint32_t)(wm * 64 * ROWB);
    const uint32_t wnRow = (uint32_t)(wn * 32 * ROWB);

    // ---- gmem sources for cp.async (512 threads) ----
    // A: row = tid>>1 (0..255), half = (tid&1)*32B, 2x16B.
    // B: row = tid>>2 (0..127), quarter = (tid&3)*16B, 1x16B.
    const char* px = (const char*)(g_xh + (size_t)(m0 + (tid >> 1)) * INF);
    const char* pw = (const char*)(g_wh + (size_t)(n0 + (tid >> 2)) * INF);
    const uint32_t aHalf = (uint32_t)(tid & 1) * 32u;
    const uint32_t bQuar = (uint32_t)(tid & 3) * 16u;
    const uint32_t aDst = sbase + (uint32_t)(tid >> 1) * ROWB + aHalf;
    const uint32_t bDst = sbase + (uint32_t)(tid >> 2) * ROWB + bQuar;

    float acc[4][4][4];
#pragma unroll
    for (int mt = 0; mt < 4; ++mt)
#pragma unroll
        for (int nt = 0; nt < 4; ++nt)
#pragma unroll
            for (int e = 0; e < 4; ++e) acc[mt][nt][e] = 0.f;

    auto load_chunk = [&](int c, int s) {
        uint32_t sb = (uint32_t)s * STAGEB;
        size_t go = (size_t)c * (BK * 2);   // byte offset within a K row
        CP16(aDst + sb + OFF_A,      px + go + aHalf);
        CP16(aDst + sb + OFF_A + 16, px + go + aHalf + 16);
        CP16(bDst + sb + OFF_B,      pw + go + bQuar);
        CP_COMMIT();
    };

    load_chunk(0, 0);
    load_chunk(1, 1);

    for (int c = 0; c < NCHUNKS; ++c) {
        if (c + 2 < NCHUNKS) CP_WAIT1(); else CP_WAIT0();
        __syncthreads();
        if (c + 2 < NCHUNKS) load_chunk(c + 2, (c + 2) % NSTAGE);

        const uint32_t st = sbase + (uint32_t)(c % NSTAGE) * STAGEB;
#pragma unroll
        for (int ks = 0; ks < 2; ++ks) {
            const uint32_t kofs = (uint32_t)ks * 32;
            uint32_t A[4][4], B[4][2];
#pragma unroll
            for (int mt = 0; mt < 4; ++mt) {
                uint32_t a = st + OFF_A + wmRow + (uint32_t)(mt * 16 * ROWB) + aOff + kofs;
                LDSM_X4(A[mt][0], A[mt][1], A[mt][2], A[mt][3], a);
            }
#pragma unroll
            for (int np = 0; np < 2; ++np) {
                uint32_t b = st + OFF_B + wnRow + (uint32_t)(np * 16 * ROWB) + bOff + kofs;
                uint32_t r0, r1, r2, r3;
                LDSM_X4(r0, r1, r2, r3, b);
                B[np * 2][0] = r0; B[np * 2][1] = r1;
                B[np * 2 + 1][0] = r2; B[np * 2 + 1][1] = r3;
            }
            // consecutive MMAs never share an accumulator (16-deep independence)
#pragma unroll
            for (int mt = 0; mt < 4; ++mt)
#pragma unroll
                for (int nt = 0; nt < 4; ++nt)
                    MMA_F16(acc[mt][nt], A[mt], B[nt]);
        }
    }

    // ---- epilogue: acc + bias -> out ----
    const int cgl = (lane & 3) * 2;
    const int r0l = lane >> 2;
    const int ncol = n0 + wn * 32 + cgl;
    const float* bp = bias + ncol;
    float2 bv[4];
#pragma unroll
    for (int nt = 0; nt < 4; ++nt) bv[nt] = *(const float2*)(bp + nt * 8);

#pragma unroll
    for (int mt = 0; mt < 4; ++mt) {
        size_t row = (size_t)(m0 + wm * 64 + mt * 16 + r0l);
        float* p0 = out + row * OUTF + ncol;
        float* p1 = p0 + (size_t)8 * OUTF;
#pragma unroll
        for (int nt = 0; nt < 4; ++nt) {
            float2 v0 = {acc[mt][nt][0] + bv[nt].x, acc[mt][nt][1] + bv[nt].y};
            float2 v1 = {acc[mt][nt][2] + bv[nt].x, acc[mt][nt][3] + bv[nt].y};
            *(float2*)(p0 + nt * 8) = v0;
            *(float2*)(p1 + nt * 8) = v1;
        }
    }
}

// ---------------- launcher ----------------
extern "C" void kernel_launch(void* const* d_in, const int* in_sizes, int n_in,
                              void* d_out, int out_size) {
    const float* x      = (const float*)d_in[0];
    const float* logits = (const float*)d_in[1];
    const float* luts   = (const float*)d_in[2];
    const float* bias   = (const float*)d_in[3];
    float* out          = (float*)d_out;
    (void)in_sizes; (void)n_in; (void)out_size;

    convert_x_kernel<<<(TOKENS * INF / 4) / 256, 256>>>(x);
    build_w_kernel<<<(OUTF * GROUPS) / 256, 256>>>(logits, luts);

    cudaFuncSetAttribute(gemm_f16_kernel, cudaFuncAttributeMaxDynamicSharedMemorySize, SMEM_BYTES);
    dim3 grid(OUTF / NTILE, TOKENS / MTILE);   // (32, 32): n fast -> W stays L2-resident
    gemm_f16_kernel<<<grid, 512, SMEM_BYTES>>>(bias, out);
}